// round 7
// baseline (speedup 1.0000x reference)
#include <cuda_runtime.h>
#include <math.h>

#define Nn 19
#define PADA 21      // eig kernel pad (conflict-free: gcd(21,32)=1)
#define PADB 20      // dense kernel pad (reads are broadcast)
#define KE 16
#define Dd 64
#define Tt 1024
#define Bb 16
#define Gg (Bb*Tt)   // 16384 graphs
#define NSWEEP 8
#define ALPHA_C 0.05f
#define HOPC 0.475f  // (1-alpha)/K
#define LN_EPS 1e-5f

// scratch (allocation-free rule: __device__ globals)
__device__ float g_anorm[(size_t)Gg*Nn*Nn];   // ~23.7 MB
__device__ float g_pe[(size_t)Gg*Nn*KE];      // ~19.9 MB

__device__ __forceinline__ float softplusf(float x){
    // jax.nn.softplus: max(x,0) + log1p(exp(-|x|))
    return fmaxf(x, 0.0f) + log1pf(expf(-fabsf(x)));
}

// ---------------------------------------------------------------------------
// Kernel A: per-graph (one warp each): a_norm + symmetrized Laplacian +
// Jacobi eigensolver (tournament ordering) + PE extraction.
// ---------------------------------------------------------------------------
__global__ void __launch_bounds__(256) eig_kernel(
    const float* __restrict__ adjacency,
    const float* __restrict__ edge_w_p,
    const float* __restrict__ edge_b_p)
{
    // per graph: M (19x21), V (19x21), AUX(96)
    __shared__ float smem[8*(2*Nn*PADA + 96)];
    const int w = threadIdx.x >> 5;
    const int l = threadIdx.x & 31;
    const int g = blockIdx.x*8 + w;

    float* M   = smem + w*(2*Nn*PADA + 96);   // adj -> identity -> EVEC
    float* V   = M + Nn*PADA;                 // w -> lapS -> diagonalized
    float* AUX = V + Nn*PADA;
    float* CS  = AUX;                         // 9 cosines
    float* SS  = AUX + 9;                     // 9 sines
    float* DIS = AUX + 18;                    // 19
    int*   ORD = (int*)(AUX + 40);            // 16
    float* SGN = AUX + 56;                    // 16

    const float ew = edge_w_p[0];
    const float eb = edge_b_p[0];
    const float* adj = adjacency + (size_t)g*Nn*Nn;

    // 1. load raw adjacency into M
    for (int i = l; i < Nn*Nn; i += 32)
        M[(i/Nn)*PADA + (i%Nn)] = adj[i];
    __syncwarp();

    // 2. edge transform: w = softplus(a*ew+eb)*mask
    for (int i = l; i < Nn*Nn; i += 32){
        int r = i/Nn, c = i%Nn;
        float a = M[r*PADA + c];
        V[r*PADA + c] = (a > 0.0f) ? softplusf(a*ew + eb) : 0.0f;
    }
    __syncwarp();
    // add_remaining_self_loops: missing diagonal -> weight 1
    if (l < Nn){
        if (!(M[l*PADA + l] > 0.0f)) V[l*PADA + l] += 1.0f;
    }
    __syncwarp();

    // 3. deg_j = column sums of w; dis = rsqrt
    if (l < Nn){
        float dsum = 0.0f;
        #pragma unroll
        for (int i = 0; i < Nn; i++) dsum += V[i*PADA + l];
        DIS[l] = (dsum > 0.0f) ? rsqrtf(fmaxf(dsum, 1e-30f)) : 0.0f;
    }
    __syncwarp();

    // 4. a_norm = dis_i * w_ij * dis_j -> global scratch
    {
        float* ga = g_anorm + (size_t)g*Nn*Nn;
        for (int i = l; i < Nn*Nn; i += 32){
            int r = i/Nn, c = i%Nn;
            ga[i] = DIS[r]*V[r*PADA + c]*DIS[c];
        }
    }
    __syncwarp();

    // 5. PE normalization: deg = max(row sums of raw adj, 1e-6)
    if (l < Nn){
        float dsum = 0.0f;
        #pragma unroll
        for (int j = 0; j < Nn; j++) dsum += M[l*PADA + j];
        DIS[l] = rsqrtf(fmaxf(dsum, 1e-6f));
    }
    __syncwarp();

    // 6. symmetrized Laplacian into V:  (1+1e-5)I - 0.5*dr_i*dr_j*(a_ij+a_ji)
    for (int i = l; i < Nn*Nn; i += 32){
        int r = i/Nn, c = i%Nn;
        float an = 0.5f * DIS[r]*DIS[c] * (M[r*PADA + c] + M[c*PADA + r]);
        V[r*PADA + c] = ((r == c) ? (1.0f + 1e-5f) : 0.0f) - an;
    }
    __syncwarp();

    // 7. M := identity (eigenvector accumulator)
    for (int i = l; i < Nn*Nn; i += 32){
        int r = i/Nn, c = i%Nn;
        M[r*PADA + c] = (r == c) ? 1.0f : 0.0f;
    }
    __syncwarp();

    // 8. Jacobi sweeps: MAT = V, EVEC = M.
    // Tournament round r pairs: {(r+k)%19, (r-k)%19}, k=1..9 (disjoint).
    for (int sweep = 0; sweep < NSWEEP; ++sweep){
        for (int r = 0; r < Nn; r++){
            if (l >= 1 && l <= 9){
                int k = l;
                int p = r + k; if (p >= Nn) p -= Nn;
                int q = r - k; if (q < 0)  q += Nn;
                float app = V[p*PADA + p];
                float aqq = V[q*PADA + q];
                float apq = V[p*PADA + q];
                float c = 1.0f, s = 0.0f;
                if (fabsf(apq) > 1e-30f){
                    float tau = (aqq - app) / (2.0f*apq);
                    float t = 1.0f / (fabsf(tau) + sqrtf(1.0f + tau*tau));
                    if (tau < 0.0f) t = -t;
                    c = rsqrtf(1.0f + t*t);
                    s = t*c;
                }
                CS[k-1] = c; SS[k-1] = s;
            }
            __syncwarp();
            // column phase on MAT (B = A*J) and EVEC (V = V*J): 342 tasks
            for (int t0 = l; t0 < 2*9*Nn; t0 += 32){
                int m = t0 / (9*Nn);
                int u = t0 % (9*Nn);
                int k = u / Nn + 1;
                int i = u % Nn;
                int p = r + k; if (p >= Nn) p -= Nn;
                int q = r - k; if (q < 0)  q += Nn;
                float c = CS[k-1], s = SS[k-1];
                float* base = m ? M : V;
                float vp = base[i*PADA + p];
                float vq = base[i*PADA + q];
                base[i*PADA + p] = c*vp - s*vq;
                base[i*PADA + q] = s*vp + c*vq;
            }
            __syncwarp();
            // row phase on MAT (A' = J^T * B): 171 tasks
            for (int t0 = l; t0 < 9*Nn; t0 += 32){
                int k = t0 / Nn + 1;
                int j = t0 % Nn;
                int p = r + k; if (p >= Nn) p -= Nn;
                int q = r - k; if (q < 0)  q += Nn;
                float c = CS[k-1], s = SS[k-1];
                float vp = V[p*PADA + j];
                float vq = V[q*PADA + j];
                V[p*PADA + j] = c*vp - s*vq;
                V[q*PADA + j] = s*vp + c*vq;
            }
            __syncwarp();
        }
    }

    // 9. rank eigenvalues ascending (stable), keep first 16
    if (l < Nn){
        float dv = V[l*PADA + l];
        int rank = 0;
        #pragma unroll
        for (int j = 0; j < Nn; j++){
            float dj = V[j*PADA + j];
            rank += (dj < dv) || (dj == dv && j < l);
        }
        if (rank < KE) ORD[rank] = l;
    }
    __syncwarp();
    // sign convention: sign of column sum (0 -> +1)
    if (l < KE){
        int i = ORD[l];
        float sum = 0.0f;
        #pragma unroll
        for (int n = 0; n < Nn; n++) sum += M[n*PADA + i];
        SGN[l] = (sum > 0.0f) ? 1.0f : ((sum < 0.0f) ? -1.0f : 1.0f);
    }
    __syncwarp();
    {
        float* gp = g_pe + (size_t)g*Nn*KE;
        for (int t0 = l; t0 < Nn*KE; t0 += 32){
            int n = t0 / KE, m = t0 % KE;
            float v = M[n*PADA + ORD[m]] * SGN[m];
            if (isnan(v)) v = 0.0f;
            else if (isinf(v)) v = (v > 0.0f) ? 1.0f : -1.0f;
            gp[t0] = v;
        }
    }
}

// ---------------------------------------------------------------------------
// Kernel B: CTA-per-graph fused SSGConv0 -> LN0 -> SSGConv1 + res -> LN1.
// Uses (A^T x) W == A^T (x W): project first, propagate in 64-d.
// Thread layout: tid -> (half = tid/64 selects node range, d = tid%64).
// ---------------------------------------------------------------------------
__global__ void __launch_bounds__(128) dense_kernel(
    const float* __restrict__ features,
    const float* __restrict__ W0, const float* __restrict__ b0,
    const float* __restrict__ W1, const float* __restrict__ b1,
    const float* __restrict__ ln0g, const float* __restrict__ ln0b,
    const float* __restrict__ ln1g, const float* __restrict__ ln1b,
    float* __restrict__ out)
{
    __shared__ float An[Nn*PADB];   // 380
    __shared__ float XC[Nn*80];     // concat(x, pe); later reused as P1 (19x64)
    __shared__ float Z0[Nn*64];
    __shared__ float Z1[Nn*64];
    __shared__ float MU[Nn], RS[Nn];

    const int g = blockIdx.x;
    const int b = g >> 10;
    const int t = g & 1023;
    const int tid = threadIdx.x;

    // load a_norm
    {
        const float* ga = g_anorm + (size_t)g*Nn*Nn;
        for (int i = tid; i < Nn*Nn; i += 128)
            An[(i/Nn)*PADB + (i%Nn)] = ga[i];
    }
    // load x: XC[n][0:64] = features[b, n, t, :]
    for (int i = tid; i < Nn*64; i += 128){
        int n = i >> 6, dd = i & 63;
        XC[n*80 + dd] = features[((size_t)((b*Nn + n)*Tt + t))*64 + dd];
    }
    // load pe: XC[n][64:80]
    {
        const float* gp = g_pe + (size_t)g*Nn*KE;
        for (int i = tid; i < Nn*KE; i += 128){
            int n = i / KE, m = i % KE;
            XC[n*80 + 64 + m] = gp[i];
        }
    }
    __syncthreads();

    const int d    = tid & 63;
    const int half = tid >> 6;
    const int n0 = half ? 10 : 0;
    const int n1 = half ? 19 : 10;

    // ---- GEMM0: Z0 = XC @ W0^T   (W0 is (64,80) row-major) ----
    {
        float wreg[80];
        #pragma unroll
        for (int f4 = 0; f4 < 20; f4++){
            float4 v = *reinterpret_cast<const float4*>(W0 + d*80 + f4*4);
            wreg[f4*4+0] = v.x; wreg[f4*4+1] = v.y;
            wreg[f4*4+2] = v.z; wreg[f4*4+3] = v.w;
        }
        for (int n = n0; n < n1; n++){
            const float4* xr = reinterpret_cast<const float4*>(XC + n*80);
            float acc = 0.0f;
            #pragma unroll
            for (int f4 = 0; f4 < 20; f4++){
                float4 x = xr[f4];
                acc += x.x*wreg[f4*4+0] + x.y*wreg[f4*4+1]
                     + x.z*wreg[f4*4+2] + x.w*wreg[f4*4+3];
            }
            Z0[n*64 + d] = acc;
        }
    }
    __syncthreads();

    // ---- hop1: Z1 = A^T Z0 ----
    {
        float zc[Nn];
        #pragma unroll
        for (int i = 0; i < Nn; i++) zc[i] = Z0[i*64 + d];
        for (int n = n0; n < n1; n++){
            float acc = 0.0f;
            #pragma unroll
            for (int i = 0; i < Nn; i++) acc += An[i*PADB + n]*zc[i];
            Z1[n*64 + d] = acc;
        }
    }
    __syncthreads();

    // ---- y0 = alpha*Z0 + C*(Z1 + A^T Z1) + b0  -> Z0 ----
    {
        float zc[Nn];
        #pragma unroll
        for (int i = 0; i < Nn; i++) zc[i] = Z1[i*64 + d];
        float bb = b0[d];
        for (int n = n0; n < n1; n++){
            float acc = 0.0f;
            #pragma unroll
            for (int i = 0; i < Nn; i++) acc += An[i*PADB + n]*zc[i];
            Z0[n*64 + d] = ALPHA_C*Z0[n*64 + d] + HOPC*(Z1[n*64 + d] + acc) + bb;
        }
    }
    __syncthreads();

    // ---- LN0 on Z0 ----
    if (tid < Nn){
        float mu = 0.0f;
        #pragma unroll
        for (int j = 0; j < 64; j++) mu += Z0[tid*64 + j];
        mu *= (1.0f/64.0f);
        float var = 0.0f;
        #pragma unroll
        for (int j = 0; j < 64; j++){ float dv = Z0[tid*64 + j] - mu; var += dv*dv; }
        var *= (1.0f/64.0f);
        MU[tid] = mu; RS[tid] = rsqrtf(var + LN_EPS);
    }
    __syncthreads();
    {
        float gg = ln0g[d], bbb = ln0b[d];
        for (int n = n0; n < n1; n++)
            Z0[n*64 + d] = (Z0[n*64 + d] - MU[n])*RS[n]*gg + bbb;
    }
    __syncthreads();

    // ---- GEMM1: Z1 = Z0 @ W1^T   (W1 is (64,64)) ----
    {
        float wreg[64];
        #pragma unroll
        for (int f4 = 0; f4 < 16; f4++){
            float4 v = *reinterpret_cast<const float4*>(W1 + d*64 + f4*4);
            wreg[f4*4+0] = v.x; wreg[f4*4+1] = v.y;
            wreg[f4*4+2] = v.z; wreg[f4*4+3] = v.w;
        }
        for (int n = n0; n < n1; n++){
            const float4* xr = reinterpret_cast<const float4*>(Z0 + n*64);
            float acc = 0.0f;
            #pragma unroll
            for (int f4 = 0; f4 < 16; f4++){
                float4 x = xr[f4];
                acc += x.x*wreg[f4*4+0] + x.y*wreg[f4*4+1]
                     + x.z*wreg[f4*4+2] + x.w*wreg[f4*4+3];
            }
            Z1[n*64 + d] = acc;
        }
    }
    __syncthreads();

    // ---- hop1: P1 (=XC region) = A^T Z1 ----
    {
        float zc[Nn];
        #pragma unroll
        for (int i = 0; i < Nn; i++) zc[i] = Z1[i*64 + d];
        for (int n = n0; n < n1; n++){
            float acc = 0.0f;
            #pragma unroll
            for (int i = 0; i < Nn; i++) acc += An[i*PADB + n]*zc[i];
            XC[n*64 + d] = acc;
        }
    }
    __syncthreads();

    // ---- y1 = alpha*Z1 + C*(P1 + A^T P1) + b1 + h0(Z0)  -> Z1 ----
    {
        float zc[Nn];
        #pragma unroll
        for (int i = 0; i < Nn; i++) zc[i] = XC[i*64 + d];
        float bb = b1[d];
        for (int n = n0; n < n1; n++){
            float acc = 0.0f;
            #pragma unroll
            for (int i = 0; i < Nn; i++) acc += An[i*PADB + n]*zc[i];
            Z1[n*64 + d] = ALPHA_C*Z1[n*64 + d] + HOPC*(XC[n*64 + d] + acc)
                         + bb + Z0[n*64 + d];
        }
    }
    __syncthreads();

    // ---- LN1 on Z1, write out ----
    if (tid < Nn){
        float mu = 0.0f;
        #pragma unroll
        for (int j = 0; j < 64; j++) mu += Z1[tid*64 + j];
        mu *= (1.0f/64.0f);
        float var = 0.0f;
        #pragma unroll
        for (int j = 0; j < 64; j++){ float dv = Z1[tid*64 + j] - mu; var += dv*dv; }
        var *= (1.0f/64.0f);
        MU[tid] = mu; RS[tid] = rsqrtf(var + LN_EPS);
    }
    __syncthreads();
    {
        float gg = ln1g[d], bbb = ln1b[d];
        for (int n = n0; n < n1; n++){
            float v = (Z1[n*64 + d] - MU[n])*RS[n]*gg + bbb;
            out[((size_t)((b*Nn + n)*Tt + t))*64 + d] = v;
        }
    }
}

// ---------------------------------------------------------------------------
extern "C" void kernel_launch(void* const* d_in, const int* in_sizes, int n_in,
                              void* d_out, int out_size)
{
    const float* features  = (const float*)d_in[0];
    const float* adjacency = (const float*)d_in[1];
    const float* edge_w    = (const float*)d_in[2];
    const float* edge_b    = (const float*)d_in[3];
    const float* gnn0_W    = (const float*)d_in[4];
    const float* gnn0_b    = (const float*)d_in[5];
    const float* gnn1_W    = (const float*)d_in[6];
    const float* gnn1_b    = (const float*)d_in[7];
    const float* ln0_g     = (const float*)d_in[8];
    const float* ln0_b     = (const float*)d_in[9];
    const float* ln1_g     = (const float*)d_in[10];
    const float* ln1_b     = (const float*)d_in[11];
    float* out = (float*)d_out;

    eig_kernel<<<Gg/8, 256>>>(adjacency, edge_w, edge_b);
    dense_kernel<<<Gg, 128>>>(features, gnn0_W, gnn0_b, gnn1_W, gnn1_b,
                              ln0_g, ln0_b, ln1_g, ln1_b, out);
}

// round 8
// speedup vs baseline: 1.4013x; 1.4013x over previous
#include <cuda_runtime.h>
#include <math.h>

#define Nn 19
#define PADA 21      // eig kernel pad (conflict-free: gcd(21,32)=1)
#define PADB 20      // dense kernel pad (reads are broadcast)
#define KE 16
#define Dd 64
#define Tt 1024
#define Bb 16
#define Gg (Bb*Tt)   // 16384 graphs
#define NSWEEP 5
#define ALPHA_C 0.05f
#define HOPC 0.475f  // (1-alpha)/K
#define LN_EPS 1e-5f

// scratch (allocation-free rule: __device__ globals)
__device__ float g_anorm[(size_t)Gg*Nn*Nn];   // ~23.7 MB
__device__ float g_pe[(size_t)Gg*Nn*KE];      // ~19.9 MB

__device__ __forceinline__ float softplusf(float x){
    // jax.nn.softplus: max(x,0) + log1p(exp(-|x|))
    return fmaxf(x, 0.0f) + log1pf(expf(-fabsf(x)));
}

// ---------------------------------------------------------------------------
// Kernel A: per-graph (one warp each): a_norm + symmetrized Laplacian +
// Jacobi eigensolver (tournament ordering) + PE extraction.
// Task decode (m,k,i per lane) hoisted out of the sweep loop into register
// arrays; only p,q depend on the round index (2 adds + 2 selects).
// ---------------------------------------------------------------------------
__global__ void __launch_bounds__(256) eig_kernel(
    const float* __restrict__ adjacency,
    const float* __restrict__ edge_w_p,
    const float* __restrict__ edge_b_p)
{
    // per graph: M (19x21), V (19x21), AUX(96)
    __shared__ float smem[8*(2*Nn*PADA + 96)];
    const int w = threadIdx.x >> 5;
    const int l = threadIdx.x & 31;
    const int g = blockIdx.x*8 + w;

    float* M   = smem + w*(2*Nn*PADA + 96);   // adj -> identity -> EVEC
    float* V   = M + Nn*PADA;                 // w -> lapS -> diagonalized
    float* AUX = V + Nn*PADA;
    float* CS  = AUX;                         // 9 cosines
    float* SS  = AUX + 9;                     // 9 sines
    float* DIS = AUX + 18;                    // 19
    int*   ORD = (int*)(AUX + 40);            // 16
    float* SGN = AUX + 56;                    // 16

    const float ew = edge_w_p[0];
    const float eb = edge_b_p[0];
    const float* adj = adjacency + (size_t)g*Nn*Nn;

    // 1. load raw adjacency into M
    for (int i = l; i < Nn*Nn; i += 32)
        M[(i/Nn)*PADA + (i%Nn)] = adj[i];
    __syncwarp();

    // 2. edge transform: w = softplus(a*ew+eb)*mask
    for (int i = l; i < Nn*Nn; i += 32){
        int r = i/Nn, c = i%Nn;
        float a = M[r*PADA + c];
        V[r*PADA + c] = (a > 0.0f) ? softplusf(a*ew + eb) : 0.0f;
    }
    __syncwarp();
    // add_remaining_self_loops: missing diagonal -> weight 1
    if (l < Nn){
        if (!(M[l*PADA + l] > 0.0f)) V[l*PADA + l] += 1.0f;
    }
    __syncwarp();

    // 3. deg_j = column sums of w; dis = rsqrt
    if (l < Nn){
        float dsum = 0.0f;
        #pragma unroll
        for (int i = 0; i < Nn; i++) dsum += V[i*PADA + l];
        DIS[l] = (dsum > 0.0f) ? rsqrtf(fmaxf(dsum, 1e-30f)) : 0.0f;
    }
    __syncwarp();

    // 4. a_norm = dis_i * w_ij * dis_j -> global scratch
    {
        float* ga = g_anorm + (size_t)g*Nn*Nn;
        for (int i = l; i < Nn*Nn; i += 32){
            int r = i/Nn, c = i%Nn;
            ga[i] = DIS[r]*V[r*PADA + c]*DIS[c];
        }
    }
    __syncwarp();

    // 5. PE normalization: deg = max(row sums of raw adj, 1e-6)
    if (l < Nn){
        float dsum = 0.0f;
        #pragma unroll
        for (int j = 0; j < Nn; j++) dsum += M[l*PADA + j];
        DIS[l] = rsqrtf(fmaxf(dsum, 1e-6f));
    }
    __syncwarp();

    // 6. symmetrized Laplacian into V:  (1+1e-5)I - 0.5*dr_i*dr_j*(a_ij+a_ji)
    for (int i = l; i < Nn*Nn; i += 32){
        int r = i/Nn, c = i%Nn;
        float an = 0.5f * DIS[r]*DIS[c] * (M[r*PADA + c] + M[c*PADA + r]);
        V[r*PADA + c] = ((r == c) ? (1.0f + 1e-5f) : 0.0f) - an;
    }
    __syncwarp();

    // 7. M := identity (eigenvector accumulator)
    for (int i = l; i < Nn*Nn; i += 32){
        int r = i/Nn, c = i%Nn;
        M[r*PADA + c] = (r == c) ? 1.0f : 0.0f;
    }
    __syncwarp();

    // --- Precompute per-lane task descriptors (round-invariant) ---
    // Column phase: 342 tasks = {matrix m in {V,M}} x {pair k=1..9} x {row i}
    float* cBase[11];
    int    cK[11];
    bool   cValid[11];
    #pragma unroll
    for (int it = 0; it < 11; ++it){
        int t0 = l + 32*it;
        cValid[it] = (t0 < 2*9*Nn);
        int tt = cValid[it] ? t0 : 0;
        int m = tt / (9*Nn);
        int u = tt % (9*Nn);
        cK[it]    = u / Nn + 1;
        cBase[it] = (m ? M : V) + (u % Nn)*PADA;
    }
    // Row phase: 171 tasks = {pair k} x {col j}, applied to V only
    int  rK[6], rJ[6];
    bool rValid[6];
    #pragma unroll
    for (int it = 0; it < 6; ++it){
        int t0 = l + 32*it;
        rValid[it] = (t0 < 9*Nn);
        int tt = rValid[it] ? t0 : 0;
        rK[it] = tt / Nn + 1;
        rJ[it] = tt % Nn;
    }

    // 8. Jacobi sweeps: MAT = V, EVEC = M.
    // Tournament round r pairs: {(r+k)%19, (r-k)%19}, k=1..9 (disjoint).
    for (int sweep = 0; sweep < NSWEEP; ++sweep){
        for (int r = 0; r < Nn; r++){
            if (l >= 1 && l <= 9){
                int k = l;
                int p = r + k; if (p >= Nn) p -= Nn;
                int q = r - k; if (q < 0)  q += Nn;
                float app = V[p*PADA + p];
                float aqq = V[q*PADA + q];
                float apq = V[p*PADA + q];
                float c = 1.0f, s = 0.0f;
                if (fabsf(apq) > 1e-30f){
                    float tau = (aqq - app) / (2.0f*apq);
                    float t = 1.0f / (fabsf(tau) + sqrtf(1.0f + tau*tau));
                    if (tau < 0.0f) t = -t;
                    c = rsqrtf(1.0f + t*t);
                    s = t*c;
                }
                CS[k-1] = c; SS[k-1] = s;
            }
            __syncwarp();
            // column phase on MAT (B = A*J) and EVEC (V = V*J)
            #pragma unroll
            for (int it = 0; it < 11; ++it){
                if (cValid[it]){
                    int k = cK[it];
                    int p = r + k; if (p >= Nn) p -= Nn;
                    int q = r - k; if (q < 0)  q += Nn;
                    float c = CS[k-1], s = SS[k-1];
                    float* base = cBase[it];
                    float vp = base[p];
                    float vq = base[q];
                    base[p] = c*vp - s*vq;
                    base[q] = s*vp + c*vq;
                }
            }
            __syncwarp();
            // row phase on MAT (A' = J^T * B)
            #pragma unroll
            for (int it = 0; it < 6; ++it){
                if (rValid[it]){
                    int k = rK[it], j = rJ[it];
                    int p = r + k; if (p >= Nn) p -= Nn;
                    int q = r - k; if (q < 0)  q += Nn;
                    float c = CS[k-1], s = SS[k-1];
                    float vp = V[p*PADA + j];
                    float vq = V[q*PADA + j];
                    V[p*PADA + j] = c*vp - s*vq;
                    V[q*PADA + j] = s*vp + c*vq;
                }
            }
            __syncwarp();
        }
    }

    // 9. rank eigenvalues ascending (stable), keep first 16
    if (l < Nn){
        float dv = V[l*PADA + l];
        int rank = 0;
        #pragma unroll
        for (int j = 0; j < Nn; j++){
            float dj = V[j*PADA + j];
            rank += (dj < dv) || (dj == dv && j < l);
        }
        if (rank < KE) ORD[rank] = l;
    }
    __syncwarp();
    // sign convention: sign of column sum (0 -> +1)
    if (l < KE){
        int i = ORD[l];
        float sum = 0.0f;
        #pragma unroll
        for (int n = 0; n < Nn; n++) sum += M[n*PADA + i];
        SGN[l] = (sum > 0.0f) ? 1.0f : ((sum < 0.0f) ? -1.0f : 1.0f);
    }
    __syncwarp();
    {
        float* gp = g_pe + (size_t)g*Nn*KE;
        for (int t0 = l; t0 < Nn*KE; t0 += 32){
            int n = t0 / KE, m = t0 % KE;
            float v = M[n*PADA + ORD[m]] * SGN[m];
            if (isnan(v)) v = 0.0f;
            else if (isinf(v)) v = (v > 0.0f) ? 1.0f : -1.0f;
            gp[t0] = v;
        }
    }
}

// ---------------------------------------------------------------------------
// Kernel B: CTA-per-graph fused SSGConv0 -> LN0 -> SSGConv1 + res -> LN1.
// Uses (A^T x) W == A^T (x W): project first, propagate in 64-d.
// Thread layout: tid -> (half = tid/64 selects node range, d = tid%64).
// ---------------------------------------------------------------------------
__global__ void __launch_bounds__(128) dense_kernel(
    const float* __restrict__ features,
    const float* __restrict__ W0, const float* __restrict__ b0,
    const float* __restrict__ W1, const float* __restrict__ b1,
    const float* __restrict__ ln0g, const float* __restrict__ ln0b,
    const float* __restrict__ ln1g, const float* __restrict__ ln1b,
    float* __restrict__ out)
{
    __shared__ float An[Nn*PADB];   // 380
    __shared__ float XC[Nn*80];     // concat(x, pe); later reused as P1 (19x64)
    __shared__ float Z0[Nn*64];
    __shared__ float Z1[Nn*64];
    __shared__ float MU[Nn], RS[Nn];

    const int g = blockIdx.x;
    const int b = g >> 10;
    const int t = g & 1023;
    const int tid = threadIdx.x;

    // load a_norm
    {
        const float* ga = g_anorm + (size_t)g*Nn*Nn;
        for (int i = tid; i < Nn*Nn; i += 128)
            An[(i/Nn)*PADB + (i%Nn)] = ga[i];
    }
    // load x: XC[n][0:64] = features[b, n, t, :]
    for (int i = tid; i < Nn*64; i += 128){
        int n = i >> 6, dd = i & 63;
        XC[n*80 + dd] = features[((size_t)((b*Nn + n)*Tt + t))*64 + dd];
    }
    // load pe: XC[n][64:80]
    {
        const float* gp = g_pe + (size_t)g*Nn*KE;
        for (int i = tid; i < Nn*KE; i += 128){
            int n = i / KE, m = i % KE;
            XC[n*80 + 64 + m] = gp[i];
        }
    }
    __syncthreads();

    const int d    = tid & 63;
    const int half = tid >> 6;
    const int n0 = half ? 10 : 0;
    const int n1 = half ? 19 : 10;

    // ---- GEMM0: Z0 = XC @ W0^T   (W0 is (64,80) row-major) ----
    {
        float wreg[80];
        #pragma unroll
        for (int f4 = 0; f4 < 20; f4++){
            float4 v = *reinterpret_cast<const float4*>(W0 + d*80 + f4*4);
            wreg[f4*4+0] = v.x; wreg[f4*4+1] = v.y;
            wreg[f4*4+2] = v.z; wreg[f4*4+3] = v.w;
        }
        for (int n = n0; n < n1; n++){
            const float4* xr = reinterpret_cast<const float4*>(XC + n*80);
            float acc = 0.0f;
            #pragma unroll
            for (int f4 = 0; f4 < 20; f4++){
                float4 x = xr[f4];
                acc += x.x*wreg[f4*4+0] + x.y*wreg[f4*4+1]
                     + x.z*wreg[f4*4+2] + x.w*wreg[f4*4+3];
            }
            Z0[n*64 + d] = acc;
        }
    }
    __syncthreads();

    // ---- hop1: Z1 = A^T Z0 ----
    {
        float zc[Nn];
        #pragma unroll
        for (int i = 0; i < Nn; i++) zc[i] = Z0[i*64 + d];
        for (int n = n0; n < n1; n++){
            float acc = 0.0f;
            #pragma unroll
            for (int i = 0; i < Nn; i++) acc += An[i*PADB + n]*zc[i];
            Z1[n*64 + d] = acc;
        }
    }
    __syncthreads();

    // ---- y0 = alpha*Z0 + C*(Z1 + A^T Z1) + b0  -> Z0 ----
    {
        float zc[Nn];
        #pragma unroll
        for (int i = 0; i < Nn; i++) zc[i] = Z1[i*64 + d];
        float bb = b0[d];
        for (int n = n0; n < n1; n++){
            float acc = 0.0f;
            #pragma unroll
            for (int i = 0; i < Nn; i++) acc += An[i*PADB + n]*zc[i];
            Z0[n*64 + d] = ALPHA_C*Z0[n*64 + d] + HOPC*(Z1[n*64 + d] + acc) + bb;
        }
    }
    __syncthreads();

    // ---- LN0 on Z0 ----
    if (tid < Nn){
        float mu = 0.0f;
        #pragma unroll
        for (int j = 0; j < 64; j++) mu += Z0[tid*64 + j];
        mu *= (1.0f/64.0f);
        float var = 0.0f;
        #pragma unroll
        for (int j = 0; j < 64; j++){ float dv = Z0[tid*64 + j] - mu; var += dv*dv; }
        var *= (1.0f/64.0f);
        MU[tid] = mu; RS[tid] = rsqrtf(var + LN_EPS);
    }
    __syncthreads();
    {
        float gg = ln0g[d], bbb = ln0b[d];
        for (int n = n0; n < n1; n++)
            Z0[n*64 + d] = (Z0[n*64 + d] - MU[n])*RS[n]*gg + bbb;
    }
    __syncthreads();

    // ---- GEMM1: Z1 = Z0 @ W1^T   (W1 is (64,64)) ----
    {
        float wreg[64];
        #pragma unroll
        for (int f4 = 0; f4 < 16; f4++){
            float4 v = *reinterpret_cast<const float4*>(W1 + d*64 + f4*4);
            wreg[f4*4+0] = v.x; wreg[f4*4+1] = v.y;
            wreg[f4*4+2] = v.z; wreg[f4*4+3] = v.w;
        }
        for (int n = n0; n < n1; n++){
            const float4* xr = reinterpret_cast<const float4*>(Z0 + n*64);
            float acc = 0.0f;
            #pragma unroll
            for (int f4 = 0; f4 < 16; f4++){
                float4 x = xr[f4];
                acc += x.x*wreg[f4*4+0] + x.y*wreg[f4*4+1]
                     + x.z*wreg[f4*4+2] + x.w*wreg[f4*4+3];
            }
            Z1[n*64 + d] = acc;
        }
    }
    __syncthreads();

    // ---- hop1: P1 (=XC region) = A^T Z1 ----
    {
        float zc[Nn];
        #pragma unroll
        for (int i = 0; i < Nn; i++) zc[i] = Z1[i*64 + d];
        for (int n = n0; n < n1; n++){
            float acc = 0.0f;
            #pragma unroll
            for (int i = 0; i < Nn; i++) acc += An[i*PADB + n]*zc[i];
            XC[n*64 + d] = acc;
        }
    }
    __syncthreads();

    // ---- y1 = alpha*Z1 + C*(P1 + A^T P1) + b1 + h0(Z0)  -> Z1 ----
    {
        float zc[Nn];
        #pragma unroll
        for (int i = 0; i < Nn; i++) zc[i] = XC[i*64 + d];
        float bb = b1[d];
        for (int n = n0; n < n1; n++){
            float acc = 0.0f;
            #pragma unroll
            for (int i = 0; i < Nn; i++) acc += An[i*PADB + n]*zc[i];
            Z1[n*64 + d] = ALPHA_C*Z1[n*64 + d] + HOPC*(XC[n*64 + d] + acc)
                         + bb + Z0[n*64 + d];
        }
    }
    __syncthreads();

    // ---- LN1 on Z1, write out ----
    if (tid < Nn){
        float mu = 0.0f;
        #pragma unroll
        for (int j = 0; j < 64; j++) mu += Z1[tid*64 + j];
        mu *= (1.0f/64.0f);
        float var = 0.0f;
        #pragma unroll
        for (int j = 0; j < 64; j++){ float dv = Z1[tid*64 + j] - mu; var += dv*dv; }
        var *= (1.0f/64.0f);
        MU[tid] = mu; RS[tid] = rsqrtf(var + LN_EPS);
    }
    __syncthreads();
    {
        float gg = ln1g[d], bbb = ln1b[d];
        for (int n = n0; n < n1; n++){
            float v = (Z1[n*64 + d] - MU[n])*RS[n]*gg + bbb;
            out[((size_t)((b*Nn + n)*Tt + t))*64 + d] = v;
        }
    }
}

// ---------------------------------------------------------------------------
extern "C" void kernel_launch(void* const* d_in, const int* in_sizes, int n_in,
                              void* d_out, int out_size)
{
    const float* features  = (const float*)d_in[0];
    const float* adjacency = (const float*)d_in[1];
    const float* edge_w    = (const float*)d_in[2];
    const float* edge_b    = (const float*)d_in[3];
    const float* gnn0_W    = (const float*)d_in[4];
    const float* gnn0_b    = (const float*)d_in[5];
    const float* gnn1_W    = (const float*)d_in[6];
    const float* gnn1_b    = (const float*)d_in[7];
    const float* ln0_g     = (const float*)d_in[8];
    const float* ln0_b     = (const float*)d_in[9];
    const float* ln1_g     = (const float*)d_in[10];
    const float* ln1_b     = (const float*)d_in[11];
    float* out = (float*)d_out;

    eig_kernel<<<Gg/8, 256>>>(adjacency, edge_w, edge_b);
    dense_kernel<<<Gg, 128>>>(features, gnn0_W, gnn0_b, gnn1_W, gnn1_b,
                              ln0_g, ln0_b, ln1_g, ln1_b, out);
}